// round 1
// baseline (speedup 1.0000x reference)
#include <cuda_runtime.h>
#include <cstdint>
#include <math.h>

#define HN 64
#define HE 64
#define NNODE 50000
#define NEDGE 200000
#define NTRI  600000
#define CC 128          // 2*HE
#define D3 320          // 3*HN + 2*HE
#define EPSF 1e-5f

// ---------------- scratch (static device arrays; no allocation) ----------------
__device__ float g_y2[(size_t)NEDGE * CC];    // c2 pre-BN linear out (E,128)
__device__ float g_y3[(size_t)NTRI * CC];     // c3 pre-BN linear out (T,128)
__device__ float g_g2[(size_t)NEDGE * HE];    // sigmoid*tanh of c2 (E,64)
__device__ float g_agg[(size_t)NEDGE * HE];   // segment-summed msg (E,64)
// sums: [0:128) c2 sum, [128:256) c2 sq, [256:384) c3 sum, [384:512) c3 sq,
//       [512:576) g2 sum, [576:640) g2 sq, [640:704) agg sum, [704:768) agg sq
__device__ float g_sumbuf[768];
// ab:   same layout but (a, b) affine coefficients per BN: y*a + b
__device__ float g_ab[768];

// ---------------- packed f32x2 helpers (sm_103a FFMA2 path) ----------------
__device__ __forceinline__ unsigned long long fma2(unsigned long long a,
                                                   unsigned long long b,
                                                   unsigned long long c) {
    unsigned long long d;
    asm("fma.rn.f32x2 %0, %1, %2, %3;" : "=l"(d) : "l"(a), "l"(b), "l"(c));
    return d;
}
__device__ __forceinline__ unsigned long long pack2(float lo, float hi) {
    unsigned long long d;
    asm("mov.b64 %0, {%1, %2};" : "=l"(d) : "f"(lo), "f"(hi));
    return d;
}
__device__ __forceinline__ float2 unpack2(unsigned long long v) {
    float2 r;
    asm("mov.b64 {%0, %1}, %2;" : "=f"(r.x), "=f"(r.y) : "l"(v));
    return r;
}

__device__ __forceinline__ float sigmoidf_(float x) {
    return 1.0f / (1.0f + __expf(-x));
}

// W shared-layout permutation: thread cg (0..15) owns cols cg*8..cg*8+7.
// Store col c at position ((c>>3)<<2) + (q&3) + ((q&4)<<4), q=c&7, so each
// 16-byte load (4 cols) across 16 lanes is a contiguous 256B conflict-free block.
__device__ __forceinline__ int wpos(int c) {
    int q = c & 7;
    return ((c >> 3) << 2) + (q & 3) + ((q & 4) << 4);
}

// ============================================================================
// K0: zero g_agg and stat sums
// ============================================================================
__global__ void k_zero() {
    size_t i = (size_t)blockIdx.x * blockDim.x + threadIdx.x;
    size_t stride = (size_t)gridDim.x * blockDim.x;
    size_t n = (size_t)NEDGE * HE;
    for (size_t p = i; p < n; p += stride) g_agg[p] = 0.0f;
    if (i < 768) g_sumbuf[i] = 0.0f;
}

// ============================================================================
// K1: c2 linear.  x = node[i]*node[j] (64), y = W2 x + b2 (128).
// Tile = 32 edges, 256 threads, persistent blocks. FFMA2 inner loop.
// ============================================================================
__global__ void __launch_bounds__(256) k_c2mm(const float* __restrict__ node,
                                              const int* __restrict__ vi,
                                              const int* __restrict__ vj,
                                              const float* __restrict__ W2,
                                              const float* __restrict__ b2) {
    __shared__ __align__(16) float sw[64 * 128];
    __shared__ __align__(16) float sx[32 * 72];
    __shared__ float sred[256];
    const int tid = threadIdx.x;

    for (int idx = tid; idx < 64 * 128; idx += 256) {
        int c = idx >> 6, k = idx & 63;
        sw[(k << 7) + wpos(c)] = W2[idx];
    }
    sred[tid] = 0.0f;

    const int cg = tid & 15;
    const int r2 = tid >> 4;
    const int r8 = tid >> 3, l8 = tid & 7;
    float bb[8];
#pragma unroll
    for (int m = 0; m < 8; m++) bb[m] = b2[cg * 8 + m];

    float sum[8], sq[8];
#pragma unroll
    for (int m = 0; m < 8; m++) { sum[m] = 0.0f; sq[m] = 0.0f; }

    const int ntiles = NEDGE / 32;
    for (int tile = blockIdx.x; tile < ntiles; tile += gridDim.x) {
        const int ebase = tile << 5;
        __syncthreads();
        {   // gather: 8 threads per edge, 8 floats each
            int e = ebase + r8;
            const float4* a = (const float4*)(node + (size_t)vi[e] * HN) + l8 * 2;
            const float4* b = (const float4*)(node + (size_t)vj[e] * HN) + l8 * 2;
            float4 a0 = a[0], a1 = a[1];
            float4 b0 = b[0], b1 = b[1];
            float4 x0 = make_float4(a0.x * b0.x, a0.y * b0.y, a0.z * b0.z, a0.w * b0.w);
            float4 x1 = make_float4(a1.x * b1.x, a1.y * b1.y, a1.z * b1.z, a1.w * b1.w);
            float* dst = sx + r8 * 72 + l8 * 8;
            *(float4*)dst = x0;
            *(float4*)(dst + 4) = x1;
        }
        __syncthreads();

        unsigned long long acc0[4], acc1[4];
#pragma unroll
        for (int p = 0; p < 4; p++) { acc0[p] = 0ull; acc1[p] = 0ull; }
        const float* x0p = sx + r2 * 72;
        const float* x1p = sx + (r2 + 16) * 72;

#pragma unroll 2
        for (int k = 0; k < 64; k += 4) {
            float4 xv0 = *(const float4*)(x0p + k);
            float4 xv1 = *(const float4*)(x1p + k);
#pragma unroll
            for (int u = 0; u < 4; u++) {
                const float* wr = sw + ((k + u) << 7) + cg * 4;
                ulonglong2 wa = *(const ulonglong2*)(wr);
                ulonglong2 wb = *(const ulonglong2*)(wr + 64);
                float f0 = (u == 0) ? xv0.x : (u == 1) ? xv0.y : (u == 2) ? xv0.z : xv0.w;
                float f1 = (u == 0) ? xv1.x : (u == 1) ? xv1.y : (u == 2) ? xv1.z : xv1.w;
                unsigned long long x00 = pack2(f0, f0);
                unsigned long long x11 = pack2(f1, f1);
                acc0[0] = fma2(x00, wa.x, acc0[0]);
                acc0[1] = fma2(x00, wa.y, acc0[1]);
                acc0[2] = fma2(x00, wb.x, acc0[2]);
                acc0[3] = fma2(x00, wb.y, acc0[3]);
                acc1[0] = fma2(x11, wa.x, acc1[0]);
                acc1[1] = fma2(x11, wa.y, acc1[1]);
                acc1[2] = fma2(x11, wb.x, acc1[2]);
                acc1[3] = fma2(x11, wb.y, acc1[3]);
            }
        }
        // epilogue: add bias, write y, accumulate stats
        float y0[8], y1[8];
#pragma unroll
        for (int p = 0; p < 4; p++) {
            float2 v0 = unpack2(acc0[p]);
            float2 v1 = unpack2(acc1[p]);
            y0[2 * p] = v0.x + bb[2 * p];  y0[2 * p + 1] = v0.y + bb[2 * p + 1];
            y1[2 * p] = v1.x + bb[2 * p];  y1[2 * p + 1] = v1.y + bb[2 * p + 1];
        }
#pragma unroll
        for (int m = 0; m < 8; m++) {
            sum[m] += y0[m] + y1[m];
            sq[m]  += y0[m] * y0[m] + y1[m] * y1[m];
        }
        size_t e0 = (size_t)(ebase + r2), e1 = e0 + 16;
        float4* o0 = (float4*)(g_y2 + e0 * CC + cg * 8);
        float4* o1 = (float4*)(g_y2 + e1 * CC + cg * 8);
        o0[0] = make_float4(y0[0], y0[1], y0[2], y0[3]);
        o0[1] = make_float4(y0[4], y0[5], y0[6], y0[7]);
        o1[0] = make_float4(y1[0], y1[1], y1[2], y1[3]);
        o1[1] = make_float4(y1[4], y1[5], y1[6], y1[7]);
    }
    __syncthreads();
#pragma unroll
    for (int m = 0; m < 8; m++) {
        atomicAdd(&sred[cg * 8 + m], sum[m]);
        atomicAdd(&sred[128 + cg * 8 + m], sq[m]);
    }
    __syncthreads();
    atomicAdd(&g_sumbuf[tid], sred[tid]);   // [0:256) = c2 sum|sq
}

// ============================================================================
// K2: c3 linear. x = concat(node[ii],node[ij],node[ik],edge[iji],edge[ikj]) (320)
// y = W3 x + b3 (128). Tile = 32 triplets. W3 fully resident in shared (160KB).
// ============================================================================
__global__ void __launch_bounds__(256) k_c3mm(const float* __restrict__ node,
                                              const float* __restrict__ edge,
                                              const int* __restrict__ ii,
                                              const int* __restrict__ ij,
                                              const int* __restrict__ ik,
                                              const int* __restrict__ iji,
                                              const int* __restrict__ ikj,
                                              const float* __restrict__ W3,
                                              const float* __restrict__ b3) {
    extern __shared__ __align__(16) float smem[];
    float* sw = smem;                 // 320*128 floats
    float* sx = smem + D3 * CC;       // 32*328 floats
    __shared__ float sred[256];
    const int tid = threadIdx.x;

    for (int idx = tid; idx < D3 * CC; idx += 256) {
        int c = idx / D3;
        int k = idx - c * D3;
        sw[k * CC + wpos(c)] = W3[idx];
    }
    sred[tid] = 0.0f;

    const int cg = tid & 15;
    const int r2 = tid >> 4;
    const int l8 = tid & 7;
    float bb[8];
#pragma unroll
    for (int m = 0; m < 8; m++) bb[m] = b3[cg * 8 + m];

    float sum[8], sq[8];
#pragma unroll
    for (int m = 0; m < 8; m++) { sum[m] = 0.0f; sq[m] = 0.0f; }

    const int ntiles = NTRI / 32;
    for (int tile = blockIdx.x; tile < ntiles; tile += gridDim.x) {
        const int tbase = tile << 5;
        __syncthreads();
        // gather 32 rows x 320 floats: 160 (row,seg) pairs, 8 threads per pair
        for (int p = tid >> 3; p < 160; p += 32) {
            int r = p / 5, s = p - r * 5;
            int t = tbase + r;
            const float* src;
            int gi;
            if (s == 0)      { gi = ii[t];  src = node; }
            else if (s == 1) { gi = ij[t];  src = node; }
            else if (s == 2) { gi = ik[t];  src = node; }
            else if (s == 3) { gi = iji[t]; src = edge; }
            else             { gi = ikj[t]; src = edge; }
            const float4* sp = (const float4*)(src + (size_t)gi * 64) + l8 * 2;
            float4 v0 = sp[0], v1 = sp[1];
            float* dst = sx + r * 328 + s * 64 + l8 * 8;
            *(float4*)dst = v0;
            *(float4*)(dst + 4) = v1;
        }
        __syncthreads();

        unsigned long long acc0[4], acc1[4];
#pragma unroll
        for (int p = 0; p < 4; p++) { acc0[p] = 0ull; acc1[p] = 0ull; }
        const float* x0p = sx + r2 * 328;
        const float* x1p = sx + (r2 + 16) * 328;

#pragma unroll 2
        for (int k = 0; k < D3; k += 4) {
            float4 xv0 = *(const float4*)(x0p + k);
            float4 xv1 = *(const float4*)(x1p + k);
#pragma unroll
            for (int u = 0; u < 4; u++) {
                const float* wr = sw + (k + u) * CC + cg * 4;
                ulonglong2 wa = *(const ulonglong2*)(wr);
                ulonglong2 wb = *(const ulonglong2*)(wr + 64);
                float f0 = (u == 0) ? xv0.x : (u == 1) ? xv0.y : (u == 2) ? xv0.z : xv0.w;
                float f1 = (u == 0) ? xv1.x : (u == 1) ? xv1.y : (u == 2) ? xv1.z : xv1.w;
                unsigned long long x00 = pack2(f0, f0);
                unsigned long long x11 = pack2(f1, f1);
                acc0[0] = fma2(x00, wa.x, acc0[0]);
                acc0[1] = fma2(x00, wa.y, acc0[1]);
                acc0[2] = fma2(x00, wb.x, acc0[2]);
                acc0[3] = fma2(x00, wb.y, acc0[3]);
                acc1[0] = fma2(x11, wa.x, acc1[0]);
                acc1[1] = fma2(x11, wa.y, acc1[1]);
                acc1[2] = fma2(x11, wb.x, acc1[2]);
                acc1[3] = fma2(x11, wb.y, acc1[3]);
            }
        }
        float y0[8], y1[8];
#pragma unroll
        for (int p = 0; p < 4; p++) {
            float2 v0 = unpack2(acc0[p]);
            float2 v1 = unpack2(acc1[p]);
            y0[2 * p] = v0.x + bb[2 * p];  y0[2 * p + 1] = v0.y + bb[2 * p + 1];
            y1[2 * p] = v1.x + bb[2 * p];  y1[2 * p + 1] = v1.y + bb[2 * p + 1];
        }
#pragma unroll
        for (int m = 0; m < 8; m++) {
            sum[m] += y0[m] + y1[m];
            sq[m]  += y0[m] * y0[m] + y1[m] * y1[m];
        }
        size_t t0 = (size_t)(tbase + r2), t1 = t0 + 16;
        float4* o0 = (float4*)(g_y3 + t0 * CC + cg * 8);
        float4* o1 = (float4*)(g_y3 + t1 * CC + cg * 8);
        o0[0] = make_float4(y0[0], y0[1], y0[2], y0[3]);
        o0[1] = make_float4(y0[4], y0[5], y0[6], y0[7]);
        o1[0] = make_float4(y1[0], y1[1], y1[2], y1[3]);
        o1[1] = make_float4(y1[4], y1[5], y1[6], y1[7]);
    }
    __syncthreads();
#pragma unroll
    for (int m = 0; m < 8; m++) {
        atomicAdd(&sred[cg * 8 + m], sum[m]);
        atomicAdd(&sred[128 + cg * 8 + m], sq[m]);
    }
    __syncthreads();
    atomicAdd(&g_sumbuf[256 + tid], sred[tid]);   // [256:512) = c3 sum|sq
}

// ============================================================================
// K3: finalize c2 / c3 BN coefficients
// ============================================================================
__global__ void k_stats1(const float* __restrict__ gc2, const float* __restrict__ bc2,
                         const float* __restrict__ gc3, const float* __restrict__ bc3) {
    int tid = threadIdx.x;  // 256
    if (tid < 128) {
        float mean = g_sumbuf[tid] * (1.0f / NEDGE);
        float var  = g_sumbuf[128 + tid] * (1.0f / NEDGE) - mean * mean;
        float a = gc2[tid] * rsqrtf(var + EPSF);
        g_ab[tid] = a;
        g_ab[128 + tid] = bc2[tid] - mean * a;
    } else {
        int c = tid - 128;
        float mean = g_sumbuf[256 + c] * (1.0f / NTRI);
        float var  = g_sumbuf[384 + c] * (1.0f / NTRI) - mean * mean;
        float a = gc3[c] * rsqrtf(var + EPSF);
        g_ab[256 + c] = a;
        g_ab[384 + c] = bc3[c] - mean * a;
    }
}

// ============================================================================
// K4: c2 activation: g2 = sigmoid(BN(y2_f)) * tanh(BN(y2_c)), + g2 stats
// ============================================================================
__global__ void __launch_bounds__(256) k_c2act() {
    __shared__ float sred[128];
    int tid = threadIdx.x;
    if (tid < 128) sred[tid] = 0.0f;
    __syncthreads();
    size_t i0 = (size_t)blockIdx.x * 256 + tid;
    int c = (int)(i0 & 63);
    float af = g_ab[c],      bf = g_ab[128 + c];
    float ac = g_ab[64 + c], bc = g_ab[192 + c];
    float s = 0.0f, q = 0.0f;
    size_t stride = (size_t)gridDim.x * 256;
    size_t n = (size_t)NEDGE * 64;
    for (size_t idx = i0; idx < n; idx += stride) {
        size_t e = idx >> 6;
        float yf = g_y2[(e << 7) + c] * af + bf;
        float yc = g_y2[(e << 7) + 64 + c] * ac + bc;
        float g = sigmoidf_(yf) * tanhf(yc);
        g_g2[idx] = g;
        s += g; q += g * g;
    }
    atomicAdd(&sred[c], s);
    atomicAdd(&sred[64 + c], q);
    __syncthreads();
    if (tid < 64) {
        atomicAdd(&g_sumbuf[512 + tid], sred[tid]);
        atomicAdd(&g_sumbuf[576 + tid], sred[64 + tid]);
    }
}

// ============================================================================
// K5: c3 activation + segment-sum scatter: agg[iji[t]] += sigmoid*tanh
// ============================================================================
__global__ void __launch_bounds__(256) k_c3act(const int* __restrict__ iji) {
    size_t i0 = (size_t)blockIdx.x * 256 + threadIdx.x;
    int c = (int)(i0 & 63);
    float af = g_ab[256 + c], bf = g_ab[384 + c];
    float ac = g_ab[320 + c], bc = g_ab[448 + c];
    size_t stride = (size_t)gridDim.x * 256;
    size_t n = (size_t)NTRI * 64;
    for (size_t idx = i0; idx < n; idx += stride) {
        size_t t = idx >> 6;
        float yf = g_y3[(t << 7) + c] * af + bf;
        float yc = g_y3[(t << 7) + 64 + c] * ac + bc;
        float msg = sigmoidf_(yf) * tanhf(yc);
        atomicAdd(&g_agg[((size_t)iji[t] << 6) + c], msg);
    }
}

// ============================================================================
// K6a: agg column stats
// ============================================================================
__global__ void __launch_bounds__(256) k_aggstats() {
    __shared__ float sred[128];
    int tid = threadIdx.x;
    if (tid < 128) sred[tid] = 0.0f;
    __syncthreads();
    size_t i0 = (size_t)blockIdx.x * 256 + tid;
    int c = (int)(i0 & 63);
    float s = 0.0f, q = 0.0f;
    size_t stride = (size_t)gridDim.x * 256;
    size_t n = (size_t)NEDGE * 64;
    for (size_t idx = i0; idx < n; idx += stride) {
        float v = g_agg[idx];
        s += v; q += v * v;
    }
    atomicAdd(&sred[c], s);
    atomicAdd(&sred[64 + c], q);
    __syncthreads();
    if (tid < 64) {
        atomicAdd(&g_sumbuf[640 + tid], sred[tid]);
        atomicAdd(&g_sumbuf[704 + tid], sred[64 + tid]);
    }
}

// ============================================================================
// K6b: finalize g2 / agg BN coefficients
// ============================================================================
__global__ void k_stats2(const float* __restrict__ g22, const float* __restrict__ b22,
                         const float* __restrict__ g32, const float* __restrict__ b32) {
    int tid = threadIdx.x;  // 128
    if (tid < 64) {
        float mean = g_sumbuf[512 + tid] * (1.0f / NEDGE);
        float var  = g_sumbuf[576 + tid] * (1.0f / NEDGE) - mean * mean;
        float a = g22[tid] * rsqrtf(var + EPSF);
        g_ab[512 + tid] = a;
        g_ab[576 + tid] = b22[tid] - mean * a;
    } else {
        int c = tid - 64;
        float mean = g_sumbuf[640 + c] * (1.0f / NEDGE);
        float var  = g_sumbuf[704 + c] * (1.0f / NEDGE) - mean * mean;
        float a = g32[c] * rsqrtf(var + EPSF);
        g_ab[640 + c] = a;
        g_ab[704 + c] = b32[c] - mean * a;
    }
}

// ============================================================================
// K7: out = tanh(edge + BN(g2) + BN(agg))
// ============================================================================
__global__ void __launch_bounds__(256) k_out(const float* __restrict__ edge,
                                             float* __restrict__ out) {
    size_t i0 = (size_t)blockIdx.x * 256 + threadIdx.x;
    int c = (int)(i0 & 63);
    float a2 = g_ab[512 + c], b2v = g_ab[576 + c];
    float a3 = g_ab[640 + c], b3v = g_ab[704 + c];
    size_t stride = (size_t)gridDim.x * 256;
    size_t n = (size_t)NEDGE * 64;
    for (size_t idx = i0; idx < n; idx += stride) {
        float v = edge[idx] + g_g2[idx] * a2 + b2v + g_agg[idx] * a3 + b3v;
        out[idx] = tanhf(v);
    }
}

// ============================================================================
extern "C" void kernel_launch(void* const* d_in, const int* in_sizes, int n_in,
                              void* d_out, int out_size) {
    const float* node   = (const float*)d_in[0];
    const float* edge   = (const float*)d_in[1];
    const int* vi       = (const int*)d_in[2];
    const int* vj       = (const int*)d_in[3];
    const int* idx_i    = (const int*)d_in[4];
    const int* idx_j    = (const int*)d_in[5];
    const int* idx_k    = (const int*)d_in[6];
    const int* idx_ji   = (const int*)d_in[7];
    const int* idx_kj   = (const int*)d_in[8];
    const float* W2     = (const float*)d_in[9];
    const float* b2     = (const float*)d_in[10];
    const float* W3     = (const float*)d_in[11];
    const float* b3     = (const float*)d_in[12];
    const float* gc2    = (const float*)d_in[13];
    const float* bc2    = (const float*)d_in[14];
    const float* gc3    = (const float*)d_in[15];
    const float* bc3    = (const float*)d_in[16];
    const float* g22    = (const float*)d_in[17];
    const float* b22    = (const float*)d_in[18];
    const float* g32    = (const float*)d_in[19];
    const float* b32    = (const float*)d_in[20];
    float* out = (float*)d_out;

    const int smem_k2 = (D3 * CC + 32 * 328) * (int)sizeof(float);  // 205824 B
    cudaFuncSetAttribute(k_c3mm, cudaFuncAttributeMaxDynamicSharedMemorySize, smem_k2);

    k_zero<<<1024, 256>>>();
    k_c2mm<<<592, 256>>>(node, vi, vj, W2, b2);
    k_c3mm<<<148, 256, smem_k2>>>(node, edge, idx_i, idx_j, idx_k, idx_ji, idx_kj, W3, b3);
    k_stats1<<<1, 256>>>(gc2, bc2, gc3, bc3);
    k_c2act<<<512, 256>>>();
    k_c3act<<<2048, 256>>>(idx_ji);
    k_aggstats<<<512, 256>>>();
    k_stats2<<<1, 128>>>(g22, b22, g32, b32);
    k_out<<<512, 256>>>(edge, out);
}

// round 2
// speedup vs baseline: 1.3188x; 1.3188x over previous
#include <cuda_runtime.h>
#include <cstdint>
#include <math.h>

#define HN 64
#define HE 64
#define NNODE 50000
#define NEDGE 200000
#define NTRI  600000
#define CC 128          // 2*HE
#define D3 320          // 3*HN + 2*HE
#define EPSF 1e-5f

// ---------------- scratch (static device arrays; no allocation) ----------------
__device__ float g_y2[(size_t)NEDGE * CC];    // c2 pre-BN linear out (E,128)
__device__ float g_y3[(size_t)NTRI * CC];     // c3 pre-BN linear out (T,128)
__device__ float g_g2[(size_t)NEDGE * HE];    // sigmoid*tanh of c2 (E,64)
__device__ float g_agg[(size_t)NEDGE * HE];   // segment-summed msg (E,64)
// sums: [0:128) c2 sum, [128:256) c2 sq, [256:384) c3 sum, [384:512) c3 sq,
//       [512:576) g2 sum, [576:640) g2 sq, [640:704) agg sum, [704:768) agg sq
__device__ float g_sumbuf[768];
// ab: (a,b) affine coefficients per BN: y*a + b  (same layout)
__device__ float g_ab[768];

// ---------------- packed f32x2 helpers (sm_103a FFMA2 path) ----------------
__device__ __forceinline__ unsigned long long fma2(unsigned long long a,
                                                   unsigned long long b,
                                                   unsigned long long c) {
    unsigned long long d;
    asm("fma.rn.f32x2 %0, %1, %2, %3;" : "=l"(d) : "l"(a), "l"(b), "l"(c));
    return d;
}
__device__ __forceinline__ unsigned long long pack2(float lo, float hi) {
    unsigned long long d;
    asm("mov.b64 %0, {%1, %2};" : "=l"(d) : "f"(lo), "f"(hi));
    return d;
}
__device__ __forceinline__ float2 unpack2(unsigned long long v) {
    float2 r;
    asm("mov.b64 {%0, %1}, %2;" : "=f"(r.x), "=f"(r.y) : "l"(v));
    return r;
}

__device__ __forceinline__ float sigmoidf_(float x) {
    return 1.0f / (1.0f + __expf(-x));
}

// W shared-layout permutation: thread cg (0..15) owns cols cg*8..cg*8+7.
// Col c stored at ((c>>3)<<2) + (q&3) + ((q&4)<<4), q=c&7: each 16B load
// across 16 lanes is a contiguous 256B conflict-free block.
__device__ __forceinline__ int wpos(int c) {
    int q = c & 7;
    return ((c >> 3) << 2) + (q & 3) + ((q & 4) << 4);
}

// ============================================================================
// K0: zero g_agg and stat sums
// ============================================================================
__global__ void k_zero() {
    size_t i = (size_t)blockIdx.x * blockDim.x + threadIdx.x;
    size_t stride = (size_t)gridDim.x * blockDim.x;
    size_t n = (size_t)NEDGE * HE / 4;
    float4 z = make_float4(0.f, 0.f, 0.f, 0.f);
    float4* p4 = (float4*)g_agg;
    for (size_t p = i; p < n; p += stride) p4[p] = z;
    if (i < 768) g_sumbuf[i] = 0.0f;
}

// ============================================================================
// K1: c2 linear.  x = node[i]*node[j] (64), y = W2 x + b2 (128).
// 64-edge tiles, 256 threads, 4 rows/thread. FFMA2 inner loop.
// ============================================================================
__global__ void __launch_bounds__(256) k_c2mm(const float* __restrict__ node,
                                              const int* __restrict__ vi,
                                              const int* __restrict__ vj,
                                              const float* __restrict__ W2,
                                              const float* __restrict__ b2) {
    extern __shared__ __align__(16) float smem2[];
    float* sw = smem2;               // 64*128 floats (32KB)
    float* sx = smem2 + 64 * CC;     // 64*72 floats (18KB)
    __shared__ float sred[256];
    const int tid = threadIdx.x;

    for (int idx = tid; idx < 64 * 128; idx += 256) {
        int c = idx >> 6, k = idx & 63;
        sw[(k << 7) + wpos(c)] = W2[idx];
    }
    sred[tid] = 0.0f;

    const int cg = tid & 15;
    const int rg = tid >> 4;       // 0..15
    const int l8 = tid & 7;
    float bb[8];
#pragma unroll
    for (int m = 0; m < 8; m++) bb[m] = b2[cg * 8 + m];

    float sum[8], sq[8];
#pragma unroll
    for (int m = 0; m < 8; m++) { sum[m] = 0.0f; sq[m] = 0.0f; }

    const int ntiles = NEDGE / 64;
    for (int tile = blockIdx.x; tile < ntiles; tile += gridDim.x) {
        const int ebase = tile << 6;
        __syncthreads();
        // gather: 8 threads per edge, 64 edges → 2 passes
        for (int p = tid >> 3; p < 64; p += 32) {
            int e = ebase + p;
            const float4* a = (const float4*)(node + (size_t)vi[e] * HN) + l8 * 2;
            const float4* b = (const float4*)(node + (size_t)vj[e] * HN) + l8 * 2;
            float4 a0 = a[0], a1 = a[1];
            float4 b0 = b[0], b1 = b[1];
            float* dst = sx + p * 72 + l8 * 8;
            *(float4*)dst = make_float4(a0.x * b0.x, a0.y * b0.y, a0.z * b0.z, a0.w * b0.w);
            *(float4*)(dst + 4) = make_float4(a1.x * b1.x, a1.y * b1.y, a1.z * b1.z, a1.w * b1.w);
        }
        __syncthreads();

        unsigned long long acc[4][4];
#pragma unroll
        for (int r = 0; r < 4; r++)
#pragma unroll
            for (int p = 0; p < 4; p++) acc[r][p] = 0ull;
        const float* xp0 = sx + rg * 72;

#pragma unroll 2
        for (int k = 0; k < 64; k += 4) {
            float4 xv[4];
            xv[0] = *(const float4*)(xp0 + k);
            xv[1] = *(const float4*)(xp0 + 16 * 72 + k);
            xv[2] = *(const float4*)(xp0 + 32 * 72 + k);
            xv[3] = *(const float4*)(xp0 + 48 * 72 + k);
#pragma unroll
            for (int u = 0; u < 4; u++) {
                const float* wr = sw + ((k + u) << 7) + cg * 4;
                ulonglong2 wa = *(const ulonglong2*)(wr);
                ulonglong2 wb = *(const ulonglong2*)(wr + 64);
#pragma unroll
                for (int r = 0; r < 4; r++) {
                    float f = (u == 0) ? xv[r].x : (u == 1) ? xv[r].y : (u == 2) ? xv[r].z : xv[r].w;
                    unsigned long long xx = pack2(f, f);
                    acc[r][0] = fma2(xx, wa.x, acc[r][0]);
                    acc[r][1] = fma2(xx, wa.y, acc[r][1]);
                    acc[r][2] = fma2(xx, wb.x, acc[r][2]);
                    acc[r][3] = fma2(xx, wb.y, acc[r][3]);
                }
            }
        }
#pragma unroll
        for (int r = 0; r < 4; r++) {
            float y[8];
#pragma unroll
            for (int p = 0; p < 4; p++) {
                float2 v = unpack2(acc[r][p]);
                y[2 * p] = v.x + bb[2 * p];
                y[2 * p + 1] = v.y + bb[2 * p + 1];
            }
#pragma unroll
            for (int m = 0; m < 8; m++) { sum[m] += y[m]; sq[m] += y[m] * y[m]; }
            size_t row = (size_t)(ebase + rg + r * 16);
            float4* o = (float4*)(g_y2 + row * CC + cg * 8);
            o[0] = make_float4(y[0], y[1], y[2], y[3]);
            o[1] = make_float4(y[4], y[5], y[6], y[7]);
        }
    }
    __syncthreads();
#pragma unroll
    for (int m = 0; m < 8; m++) {
        atomicAdd(&sred[cg * 8 + m], sum[m]);
        atomicAdd(&sred[128 + cg * 8 + m], sq[m]);
    }
    __syncthreads();
    atomicAdd(&g_sumbuf[tid], sred[tid]);   // [0:256) = c2 sum|sq
}

// ============================================================================
// K2: c3 linear. x = concat(node[ii],node[ij],node[ik],edge[iji],edge[ikj]) (320)
// y = W3 x + b3 (128). 48-triplet tiles, 3 rows/thread, W3 resident (160KB).
// ============================================================================
__global__ void __launch_bounds__(256) k_c3mm(const float* __restrict__ node,
                                              const float* __restrict__ edge,
                                              const int* __restrict__ ii,
                                              const int* __restrict__ ij,
                                              const int* __restrict__ ik,
                                              const int* __restrict__ iji,
                                              const int* __restrict__ ikj,
                                              const float* __restrict__ W3,
                                              const float* __restrict__ b3) {
    extern __shared__ __align__(16) float smem[];
    float* sw = smem;                 // 320*128 floats (160KB)
    float* sx = smem + D3 * CC;       // 48*324 floats (62KB)
    __shared__ float sred[256];
    const int tid = threadIdx.x;

    for (int idx = tid; idx < D3 * CC; idx += 256) {
        int c = idx / D3;
        int k = idx - c * D3;
        sw[k * CC + wpos(c)] = W3[idx];
    }
    sred[tid] = 0.0f;

    const int cg = tid & 15;
    const int rg = tid >> 4;         // 0..15
    const int l8 = tid & 7;
    float bb[8];
#pragma unroll
    for (int m = 0; m < 8; m++) bb[m] = b3[cg * 8 + m];

    float sum[8], sq[8];
#pragma unroll
    for (int m = 0; m < 8; m++) { sum[m] = 0.0f; sq[m] = 0.0f; }

    const int ntiles = NTRI / 48;
    for (int tile = blockIdx.x; tile < ntiles; tile += gridDim.x) {
        const int tbase = tile * 48;
        __syncthreads();
        // gather 48 rows x 320 floats: 240 (row,seg) pairs, 8 threads per pair
        for (int p = tid >> 3; p < 240; p += 32) {
            int r = p / 5, s = p - r * 5;
            int t = tbase + r;
            const float* src;
            int gi;
            if (s == 0)      { gi = ii[t];  src = node; }
            else if (s == 1) { gi = ij[t];  src = node; }
            else if (s == 2) { gi = ik[t];  src = node; }
            else if (s == 3) { gi = iji[t]; src = edge; }
            else             { gi = ikj[t]; src = edge; }
            const float4* sp = (const float4*)(src + (size_t)gi * 64) + l8 * 2;
            float4 v0 = sp[0], v1 = sp[1];
            float* dst = sx + r * 324 + s * 64 + l8 * 8;
            *(float4*)dst = v0;
            *(float4*)(dst + 4) = v1;
        }
        __syncthreads();

        unsigned long long acc[3][4];
#pragma unroll
        for (int r = 0; r < 3; r++)
#pragma unroll
            for (int p = 0; p < 4; p++) acc[r][p] = 0ull;
        const float* xp0 = sx + rg * 324;

#pragma unroll 2
        for (int k = 0; k < D3; k += 4) {
            float4 xv[3];
            xv[0] = *(const float4*)(xp0 + k);
            xv[1] = *(const float4*)(xp0 + 16 * 324 + k);
            xv[2] = *(const float4*)(xp0 + 32 * 324 + k);
#pragma unroll
            for (int u = 0; u < 4; u++) {
                const float* wr = sw + (k + u) * CC + cg * 4;
                ulonglong2 wa = *(const ulonglong2*)(wr);
                ulonglong2 wb = *(const ulonglong2*)(wr + 64);
#pragma unroll
                for (int r = 0; r < 3; r++) {
                    float f = (u == 0) ? xv[r].x : (u == 1) ? xv[r].y : (u == 2) ? xv[r].z : xv[r].w;
                    unsigned long long xx = pack2(f, f);
                    acc[r][0] = fma2(xx, wa.x, acc[r][0]);
                    acc[r][1] = fma2(xx, wa.y, acc[r][1]);
                    acc[r][2] = fma2(xx, wb.x, acc[r][2]);
                    acc[r][3] = fma2(xx, wb.y, acc[r][3]);
                }
            }
        }
#pragma unroll
        for (int r = 0; r < 3; r++) {
            float y[8];
#pragma unroll
            for (int p = 0; p < 4; p++) {
                float2 v = unpack2(acc[r][p]);
                y[2 * p] = v.x + bb[2 * p];
                y[2 * p + 1] = v.y + bb[2 * p + 1];
            }
#pragma unroll
            for (int m = 0; m < 8; m++) { sum[m] += y[m]; sq[m] += y[m] * y[m]; }
            size_t row = (size_t)(tbase + rg + r * 16);
            float4* o = (float4*)(g_y3 + row * CC + cg * 8);
            o[0] = make_float4(y[0], y[1], y[2], y[3]);
            o[1] = make_float4(y[4], y[5], y[6], y[7]);
        }
    }
    __syncthreads();
#pragma unroll
    for (int m = 0; m < 8; m++) {
        atomicAdd(&sred[cg * 8 + m], sum[m]);
        atomicAdd(&sred[128 + cg * 8 + m], sq[m]);
    }
    __syncthreads();
    atomicAdd(&g_sumbuf[256 + tid], sred[tid]);   // [256:512) = c3 sum|sq
}

// ============================================================================
// K3: finalize c2 / c3 BN coefficients
// ============================================================================
__global__ void k_stats1(const float* __restrict__ gc2, const float* __restrict__ bc2,
                         const float* __restrict__ gc3, const float* __restrict__ bc3) {
    int tid = threadIdx.x;  // 256
    if (tid < 128) {
        float mean = g_sumbuf[tid] * (1.0f / NEDGE);
        float var  = g_sumbuf[128 + tid] * (1.0f / NEDGE) - mean * mean;
        float a = gc2[tid] * rsqrtf(var + EPSF);
        g_ab[tid] = a;
        g_ab[128 + tid] = bc2[tid] - mean * a;
    } else {
        int c = tid - 128;
        float mean = g_sumbuf[256 + c] * (1.0f / NTRI);
        float var  = g_sumbuf[384 + c] * (1.0f / NTRI) - mean * mean;
        float a = gc3[c] * rsqrtf(var + EPSF);
        g_ab[256 + c] = a;
        g_ab[384 + c] = bc3[c] - mean * a;
    }
}

// ============================================================================
// K4: c2 activation: g2 = sigmoid(BN(y2_f)) * tanh(BN(y2_c)), + g2 stats
// One thread per (edge, 4-col group). float4 loads/stores.
// ============================================================================
__global__ void __launch_bounds__(256) k_c2act() {
    __shared__ float sred[128];
    int tid = threadIdx.x;
    if (tid < 128) sred[tid] = 0.0f;
    __syncthreads();
    size_t i0 = (size_t)blockIdx.x * 256 + tid;
    int c = (int)(i0 & 15) * 4;
    float4 af = *(const float4*)&g_ab[c];
    float4 bf = *(const float4*)&g_ab[128 + c];
    float4 ac = *(const float4*)&g_ab[64 + c];
    float4 bc = *(const float4*)&g_ab[192 + c];
    float s[4] = {0, 0, 0, 0}, q[4] = {0, 0, 0, 0};
    size_t stride = (size_t)gridDim.x * 256;
    size_t n = (size_t)NEDGE * 16;
    for (size_t idx = i0; idx < n; idx += stride) {
        size_t e = idx >> 4;
        float4 yf = *(const float4*)&g_y2[(e << 7) + c];
        float4 yc = *(const float4*)&g_y2[(e << 7) + 64 + c];
        float4 g;
        g.x = sigmoidf_(yf.x * af.x + bf.x) * tanhf(yc.x * ac.x + bc.x);
        g.y = sigmoidf_(yf.y * af.y + bf.y) * tanhf(yc.y * ac.y + bc.y);
        g.z = sigmoidf_(yf.z * af.z + bf.z) * tanhf(yc.z * ac.z + bc.z);
        g.w = sigmoidf_(yf.w * af.w + bf.w) * tanhf(yc.w * ac.w + bc.w);
        *(float4*)&g_g2[idx << 2] = g;
        s[0] += g.x; s[1] += g.y; s[2] += g.z; s[3] += g.w;
        q[0] += g.x * g.x; q[1] += g.y * g.y; q[2] += g.z * g.z; q[3] += g.w * g.w;
    }
#pragma unroll
    for (int u = 0; u < 4; u++) {
        atomicAdd(&sred[c + u], s[u]);
        atomicAdd(&sred[64 + c + u], q[u]);
    }
    __syncthreads();
    if (tid < 128) atomicAdd(&g_sumbuf[512 + tid], sred[tid]);
}

// ============================================================================
// K5: c3 activation + segment-sum scatter: agg[iji[t]] += sigmoid*tanh
// One thread per (triplet, 4-col group); vector red.global.add
// ============================================================================
__global__ void __launch_bounds__(256) k_c3act(const int* __restrict__ iji) {
    size_t i0 = (size_t)blockIdx.x * 256 + threadIdx.x;
    int c = (int)(i0 & 15) * 4;
    float4 af = *(const float4*)&g_ab[256 + c];
    float4 bf = *(const float4*)&g_ab[384 + c];
    float4 ac = *(const float4*)&g_ab[320 + c];
    float4 bc = *(const float4*)&g_ab[448 + c];
    size_t stride = (size_t)gridDim.x * 256;
    size_t n = (size_t)NTRI * 16;
    for (size_t idx = i0; idx < n; idx += stride) {
        size_t t = idx >> 4;
        float4 yf = *(const float4*)&g_y3[(t << 7) + c];
        float4 yc = *(const float4*)&g_y3[(t << 7) + 64 + c];
        float m0 = sigmoidf_(yf.x * af.x + bf.x) * tanhf(yc.x * ac.x + bc.x);
        float m1 = sigmoidf_(yf.y * af.y + bf.y) * tanhf(yc.y * ac.y + bc.y);
        float m2 = sigmoidf_(yf.z * af.z + bf.z) * tanhf(yc.z * ac.z + bc.z);
        float m3 = sigmoidf_(yf.w * af.w + bf.w) * tanhf(yc.w * ac.w + bc.w);
        float* dst = g_agg + ((size_t)iji[t] << 6) + c;
        asm volatile("red.global.v4.f32.add [%0], {%1, %2, %3, %4};"
                     :: "l"(dst), "f"(m0), "f"(m1), "f"(m2), "f"(m3) : "memory");
    }
}

// ============================================================================
// K6a: agg column stats (float4)
// ============================================================================
__global__ void __launch_bounds__(256) k_aggstats() {
    __shared__ float sred[128];
    int tid = threadIdx.x;
    if (tid < 128) sred[tid] = 0.0f;
    __syncthreads();
    size_t i0 = (size_t)blockIdx.x * 256 + tid;
    int c = (int)(i0 & 15) * 4;
    float s[4] = {0, 0, 0, 0}, q[4] = {0, 0, 0, 0};
    size_t stride = (size_t)gridDim.x * 256;
    size_t n = (size_t)NEDGE * 16;
    for (size_t idx = i0; idx < n; idx += stride) {
        float4 v = *(const float4*)&g_agg[idx << 2];
        s[0] += v.x; s[1] += v.y; s[2] += v.z; s[3] += v.w;
        q[0] += v.x * v.x; q[1] += v.y * v.y; q[2] += v.z * v.z; q[3] += v.w * v.w;
    }
#pragma unroll
    for (int u = 0; u < 4; u++) {
        atomicAdd(&sred[c + u], s[u]);
        atomicAdd(&sred[64 + c + u], q[u]);
    }
    __syncthreads();
    if (tid < 128) atomicAdd(&g_sumbuf[640 + tid], sred[tid]);
}

// ============================================================================
// K6b: finalize g2 / agg BN coefficients
// ============================================================================
__global__ void k_stats2(const float* __restrict__ g22, const float* __restrict__ b22,
                         const float* __restrict__ g32, const float* __restrict__ b32) {
    int tid = threadIdx.x;  // 128
    if (tid < 64) {
        float mean = g_sumbuf[512 + tid] * (1.0f / NEDGE);
        float var  = g_sumbuf[576 + tid] * (1.0f / NEDGE) - mean * mean;
        float a = g22[tid] * rsqrtf(var + EPSF);
        g_ab[512 + tid] = a;
        g_ab[576 + tid] = b22[tid] - mean * a;
    } else {
        int c = tid - 64;
        float mean = g_sumbuf[640 + c] * (1.0f / NEDGE);
        float var  = g_sumbuf[704 + c] * (1.0f / NEDGE) - mean * mean;
        float a = g32[c] * rsqrtf(var + EPSF);
        g_ab[640 + c] = a;
        g_ab[704 + c] = b32[c] - mean * a;
    }
}

// ============================================================================
// K7: out = tanh(edge + BN(g2) + BN(agg))  (float4)
// ============================================================================
__global__ void __launch_bounds__(256) k_out(const float* __restrict__ edge,
                                             float* __restrict__ out) {
    size_t i0 = (size_t)blockIdx.x * 256 + threadIdx.x;
    int c = (int)(i0 & 15) * 4;
    float4 a2 = *(const float4*)&g_ab[512 + c];
    float4 b2v = *(const float4*)&g_ab[576 + c];
    float4 a3 = *(const float4*)&g_ab[640 + c];
    float4 b3v = *(const float4*)&g_ab[704 + c];
    size_t stride = (size_t)gridDim.x * 256;
    size_t n = (size_t)NEDGE * 16;
    for (size_t idx = i0; idx < n; idx += stride) {
        float4 e = *(const float4*)&edge[idx << 2];
        float4 g = *(const float4*)&g_g2[idx << 2];
        float4 a = *(const float4*)&g_agg[idx << 2];
        float4 o;
        o.x = tanhf(e.x + g.x * a2.x + b2v.x + a.x * a3.x + b3v.x);
        o.y = tanhf(e.y + g.y * a2.y + b2v.y + a.y * a3.y + b3v.y);
        o.z = tanhf(e.z + g.z * a2.z + b2v.z + a.z * a3.z + b3v.z);
        o.w = tanhf(e.w + g.w * a2.w + b2v.w + a.w * a3.w + b3v.w);
        *(float4*)&out[idx << 2] = o;
    }
}

// ============================================================================
extern "C" void kernel_launch(void* const* d_in, const int* in_sizes, int n_in,
                              void* d_out, int out_size) {
    const float* node   = (const float*)d_in[0];
    const float* edge   = (const float*)d_in[1];
    const int* vi       = (const int*)d_in[2];
    const int* vj       = (const int*)d_in[3];
    const int* idx_i    = (const int*)d_in[4];
    const int* idx_j    = (const int*)d_in[5];
    const int* idx_k    = (const int*)d_in[6];
    const int* idx_ji   = (const int*)d_in[7];
    const int* idx_kj   = (const int*)d_in[8];
    const float* W2     = (const float*)d_in[9];
    const float* b2     = (const float*)d_in[10];
    const float* W3     = (const float*)d_in[11];
    const float* b3     = (const float*)d_in[12];
    const float* gc2    = (const float*)d_in[13];
    const float* bc2    = (const float*)d_in[14];
    const float* gc3    = (const float*)d_in[15];
    const float* bc3    = (const float*)d_in[16];
    const float* g22    = (const float*)d_in[17];
    const float* b22    = (const float*)d_in[18];
    const float* g32    = (const float*)d_in[19];
    const float* b32    = (const float*)d_in[20];
    float* out = (float*)d_out;

    const int smem_k3 = (D3 * CC + 48 * 324) * (int)sizeof(float);   // 226048 B
    const int smem_k1 = (64 * CC + 64 * 72) * (int)sizeof(float);    // 51200 B
    cudaFuncSetAttribute(k_c3mm, cudaFuncAttributeMaxDynamicSharedMemorySize, smem_k3);
    cudaFuncSetAttribute(k_c2mm, cudaFuncAttributeMaxDynamicSharedMemorySize, smem_k1);

    k_zero<<<1024, 256>>>();
    k_c2mm<<<592, 256, smem_k1>>>(node, vi, vj, W2, b2);
    k_c3mm<<<148, 256, smem_k3>>>(node, edge, idx_i, idx_j, idx_k, idx_ji, idx_kj, W3, b3);
    k_stats1<<<1, 256>>>(gc2, bc2, gc3, bc3);
    k_c2act<<<512, 256>>>();
    k_c3act<<<2048, 256>>>(idx_ji);
    k_aggstats<<<512, 256>>>();
    k_stats2<<<1, 128>>>(g22, b22, g32, b32);
    k_out<<<512, 256>>>(edge, out);
}

// round 3
// speedup vs baseline: 1.3188x; 1.0000x over previous
#include <cuda_runtime.h>
#include <cstdint>
#include <math.h>

#define HN 64
#define HE 64
#define NNODE 50000
#define NEDGE 200000
#define NTRI  600000
#define CC 128          // 2*HE
#define D3 320          // 3*HN + 2*HE
#define EPSF 1e-5f

// ---------------- scratch (static device arrays; no allocation) ----------------
__device__ float g_y2[(size_t)NEDGE * CC];    // c2 pre-BN linear out (E,128)
__device__ float g_y3[(size_t)NTRI * CC];     // c3 pre-BN linear out (T,128)
__device__ float g_g2[(size_t)NEDGE * HE];    // sigmoid*tanh of c2 (E,64)
__device__ float g_agg[(size_t)NEDGE * HE];   // segment-summed msg (E,64)
// sums: [0:128) c2 sum, [128:256) c2 sq, [256:384) c3 sum, [384:512) c3 sq,
//       [512:576) g2 sum, [576:640) g2 sq, [640:704) agg sum, [704:768) agg sq
__device__ float g_sumbuf[768];
// ab: (a,b) affine coefficients per BN: y*a + b  (same layout)
__device__ float g_ab[768];

// ---------------- packed f32x2 helpers (sm_103a FFMA2 path) ----------------
__device__ __forceinline__ unsigned long long fma2(unsigned long long a,
                                                   unsigned long long b,
                                                   unsigned long long c) {
    unsigned long long d;
    asm("fma.rn.f32x2 %0, %1, %2, %3;" : "=l"(d) : "l"(a), "l"(b), "l"(c));
    return d;
}
__device__ __forceinline__ unsigned long long pack2(float lo, float hi) {
    unsigned long long d;
    asm("mov.b64 %0, {%1, %2};" : "=l"(d) : "f"(lo), "f"(hi));
    return d;
}
__device__ __forceinline__ float2 unpack2(unsigned long long v) {
    float2 r;
    asm("mov.b64 {%0, %1}, %2;" : "=f"(r.x), "=f"(r.y) : "l"(v));
    return r;
}

__device__ __forceinline__ float sigmoidf_(float x) {
    return 1.0f / (1.0f + __expf(-x));
}

// W shared-layout permutation: thread cg (0..15) owns cols cg*8..cg*8+7.
// Col c stored at ((c>>3)<<2) + (q&3) + ((q&4)<<4), q=c&7: each 16B load
// across 16 lanes is a contiguous 256B conflict-free block.
__device__ __forceinline__ int wpos(int c) {
    int q = c & 7;
    return ((c >> 3) << 2) + (q & 3) + ((q & 4) << 4);
}

// ============================================================================
// K0: zero g_agg and stat sums
// ============================================================================
__global__ void k_zero() {
    size_t i = (size_t)blockIdx.x * blockDim.x + threadIdx.x;
    size_t stride = (size_t)gridDim.x * blockDim.x;
    size_t n = (size_t)NEDGE * HE / 4;
    float4 z = make_float4(0.f, 0.f, 0.f, 0.f);
    float4* p4 = (float4*)g_agg;
    for (size_t p = i; p < n; p += stride) p4[p] = z;
    if (i < 768) g_sumbuf[i] = 0.0f;
}

// ============================================================================
// K1: c2 linear.  x = node[i]*node[j] (64), y = W2 x + b2 (128).
// 64-edge tiles, 256 threads, 4 rows/thread. FFMA2 inner loop.
// ============================================================================
__global__ void __launch_bounds__(256) k_c2mm(const float* __restrict__ node,
                                              const int* __restrict__ vi,
                                              const int* __restrict__ vj,
                                              const float* __restrict__ W2,
                                              const float* __restrict__ b2) {
    extern __shared__ __align__(16) float smem2[];
    float* sw = smem2;               // 64*128 floats (32KB)
    float* sx = smem2 + 64 * CC;     // 64*72 floats (18KB)
    __shared__ float sred[256];
    const int tid = threadIdx.x;

    for (int idx = tid; idx < 64 * 128; idx += 256) {
        int c = idx >> 6, k = idx & 63;
        sw[(k << 7) + wpos(c)] = W2[idx];
    }
    sred[tid] = 0.0f;

    const int cg = tid & 15;
    const int rg = tid >> 4;       // 0..15
    const int l8 = tid & 7;
    float bb[8];
#pragma unroll
    for (int m = 0; m < 8; m++) bb[m] = b2[cg * 8 + m];

    float sum[8], sq[8];
#pragma unroll
    for (int m = 0; m < 8; m++) { sum[m] = 0.0f; sq[m] = 0.0f; }

    const int ntiles = NEDGE / 64;
    for (int tile = blockIdx.x; tile < ntiles; tile += gridDim.x) {
        const int ebase = tile << 6;
        __syncthreads();
        // gather: 8 threads per edge, 64 edges → 2 passes
        for (int p = tid >> 3; p < 64; p += 32) {
            int e = ebase + p;
            const float4* a = (const float4*)(node + (size_t)vi[e] * HN) + l8 * 2;
            const float4* b = (const float4*)(node + (size_t)vj[e] * HN) + l8 * 2;
            float4 a0 = a[0], a1 = a[1];
            float4 b0 = b[0], b1 = b[1];
            float* dst = sx + p * 72 + l8 * 8;
            *(float4*)dst = make_float4(a0.x * b0.x, a0.y * b0.y, a0.z * b0.z, a0.w * b0.w);
            *(float4*)(dst + 4) = make_float4(a1.x * b1.x, a1.y * b1.y, a1.z * b1.z, a1.w * b1.w);
        }
        __syncthreads();

        unsigned long long acc[4][4];
#pragma unroll
        for (int r = 0; r < 4; r++)
#pragma unroll
            for (int p = 0; p < 4; p++) acc[r][p] = 0ull;
        const float* xp0 = sx + rg * 72;

#pragma unroll 2
        for (int k = 0; k < 64; k += 4) {
            float4 xv[4];
            xv[0] = *(const float4*)(xp0 + k);
            xv[1] = *(const float4*)(xp0 + 16 * 72 + k);
            xv[2] = *(const float4*)(xp0 + 32 * 72 + k);
            xv[3] = *(const float4*)(xp0 + 48 * 72 + k);
#pragma unroll
            for (int u = 0; u < 4; u++) {
                const float* wr = sw + ((k + u) << 7) + cg * 4;
                ulonglong2 wa = *(const ulonglong2*)(wr);
                ulonglong2 wb = *(const ulonglong2*)(wr + 64);
#pragma unroll
                for (int r = 0; r < 4; r++) {
                    float f = (u == 0) ? xv[r].x : (u == 1) ? xv[r].y : (u == 2) ? xv[r].z : xv[r].w;
                    unsigned long long xx = pack2(f, f);
                    acc[r][0] = fma2(xx, wa.x, acc[r][0]);
                    acc[r][1] = fma2(xx, wa.y, acc[r][1]);
                    acc[r][2] = fma2(xx, wb.x, acc[r][2]);
                    acc[r][3] = fma2(xx, wb.y, acc[r][3]);
                }
            }
        }
#pragma unroll
        for (int r = 0; r < 4; r++) {
            float y[8];
#pragma unroll
            for (int p = 0; p < 4; p++) {
                float2 v = unpack2(acc[r][p]);
                y[2 * p] = v.x + bb[2 * p];
                y[2 * p + 1] = v.y + bb[2 * p + 1];
            }
#pragma unroll
            for (int m = 0; m < 8; m++) { sum[m] += y[m]; sq[m] += y[m] * y[m]; }
            size_t row = (size_t)(ebase + rg + r * 16);
            float4* o = (float4*)(g_y2 + row * CC + cg * 8);
            o[0] = make_float4(y[0], y[1], y[2], y[3]);
            o[1] = make_float4(y[4], y[5], y[6], y[7]);
        }
    }
    __syncthreads();
#pragma unroll
    for (int m = 0; m < 8; m++) {
        atomicAdd(&sred[cg * 8 + m], sum[m]);
        atomicAdd(&sred[128 + cg * 8 + m], sq[m]);
    }
    __syncthreads();
    atomicAdd(&g_sumbuf[tid], sred[tid]);   // [0:256) = c2 sum|sq
}

// ============================================================================
// K2: c3 linear. x = concat(node[ii],node[ij],node[ik],edge[iji],edge[ikj]) (320)
// y = W3 x + b3 (128). 48-triplet tiles, 3 rows/thread, W3 resident (160KB).
// ============================================================================
__global__ void __launch_bounds__(256) k_c3mm(const float* __restrict__ node,
                                              const float* __restrict__ edge,
                                              const int* __restrict__ ii,
                                              const int* __restrict__ ij,
                                              const int* __restrict__ ik,
                                              const int* __restrict__ iji,
                                              const int* __restrict__ ikj,
                                              const float* __restrict__ W3,
                                              const float* __restrict__ b3) {
    extern __shared__ __align__(16) float smem[];
    float* sw = smem;                 // 320*128 floats (160KB)
    float* sx = smem + D3 * CC;       // 48*324 floats (62KB)
    __shared__ float sred[256];
    const int tid = threadIdx.x;

    for (int idx = tid; idx < D3 * CC; idx += 256) {
        int c = idx / D3;
        int k = idx - c * D3;
        sw[k * CC + wpos(c)] = W3[idx];
    }
    sred[tid] = 0.0f;

    const int cg = tid & 15;
    const int rg = tid >> 4;         // 0..15
    const int l8 = tid & 7;
    float bb[8];
#pragma unroll
    for (int m = 0; m < 8; m++) bb[m] = b3[cg * 8 + m];

    float sum[8], sq[8];
#pragma unroll
    for (int m = 0; m < 8; m++) { sum[m] = 0.0f; sq[m] = 0.0f; }

    const int ntiles = NTRI / 48;
    for (int tile = blockIdx.x; tile < ntiles; tile += gridDim.x) {
        const int tbase = tile * 48;
        __syncthreads();
        // gather 48 rows x 320 floats: 240 (row,seg) pairs, 8 threads per pair
        for (int p = tid >> 3; p < 240; p += 32) {
            int r = p / 5, s = p - r * 5;
            int t = tbase + r;
            const float* src;
            int gi;
            if (s == 0)      { gi = ii[t];  src = node; }
            else if (s == 1) { gi = ij[t];  src = node; }
            else if (s == 2) { gi = ik[t];  src = node; }
            else if (s == 3) { gi = iji[t]; src = edge; }
            else             { gi = ikj[t]; src = edge; }
            const float4* sp = (const float4*)(src + (size_t)gi * 64) + l8 * 2;
            float4 v0 = sp[0], v1 = sp[1];
            float* dst = sx + r * 324 + s * 64 + l8 * 8;
            *(float4*)dst = v0;
            *(float4*)(dst + 4) = v1;
        }
        __syncthreads();

        unsigned long long acc[3][4];
#pragma unroll
        for (int r = 0; r < 3; r++)
#pragma unroll
            for (int p = 0; p < 4; p++) acc[r][p] = 0ull;
        const float* xp0 = sx + rg * 324;

#pragma unroll 2
        for (int k = 0; k < D3; k += 4) {
            float4 xv[3];
            xv[0] = *(const float4*)(xp0 + k);
            xv[1] = *(const float4*)(xp0 + 16 * 324 + k);
            xv[2] = *(const float4*)(xp0 + 32 * 324 + k);
#pragma unroll
            for (int u = 0; u < 4; u++) {
                const float* wr = sw + (k + u) * CC + cg * 4;
                ulonglong2 wa = *(const ulonglong2*)(wr);
                ulonglong2 wb = *(const ulonglong2*)(wr + 64);
#pragma unroll
                for (int r = 0; r < 3; r++) {
                    float f = (u == 0) ? xv[r].x : (u == 1) ? xv[r].y : (u == 2) ? xv[r].z : xv[r].w;
                    unsigned long long xx = pack2(f, f);
                    acc[r][0] = fma2(xx, wa.x, acc[r][0]);
                    acc[r][1] = fma2(xx, wa.y, acc[r][1]);
                    acc[r][2] = fma2(xx, wb.x, acc[r][2]);
                    acc[r][3] = fma2(xx, wb.y, acc[r][3]);
                }
            }
        }
#pragma unroll
        for (int r = 0; r < 3; r++) {
            float y[8];
#pragma unroll
            for (int p = 0; p < 4; p++) {
                float2 v = unpack2(acc[r][p]);
                y[2 * p] = v.x + bb[2 * p];
                y[2 * p + 1] = v.y + bb[2 * p + 1];
            }
#pragma unroll
            for (int m = 0; m < 8; m++) { sum[m] += y[m]; sq[m] += y[m] * y[m]; }
            size_t row = (size_t)(tbase + rg + r * 16);
            float4* o = (float4*)(g_y3 + row * CC + cg * 8);
            o[0] = make_float4(y[0], y[1], y[2], y[3]);
            o[1] = make_float4(y[4], y[5], y[6], y[7]);
        }
    }
    __syncthreads();
#pragma unroll
    for (int m = 0; m < 8; m++) {
        atomicAdd(&sred[cg * 8 + m], sum[m]);
        atomicAdd(&sred[128 + cg * 8 + m], sq[m]);
    }
    __syncthreads();
    atomicAdd(&g_sumbuf[256 + tid], sred[tid]);   // [256:512) = c3 sum|sq
}

// ============================================================================
// K3: finalize c2 / c3 BN coefficients
// ============================================================================
__global__ void k_stats1(const float* __restrict__ gc2, const float* __restrict__ bc2,
                         const float* __restrict__ gc3, const float* __restrict__ bc3) {
    int tid = threadIdx.x;  // 256
    if (tid < 128) {
        float mean = g_sumbuf[tid] * (1.0f / NEDGE);
        float var  = g_sumbuf[128 + tid] * (1.0f / NEDGE) - mean * mean;
        float a = gc2[tid] * rsqrtf(var + EPSF);
        g_ab[tid] = a;
        g_ab[128 + tid] = bc2[tid] - mean * a;
    } else {
        int c = tid - 128;
        float mean = g_sumbuf[256 + c] * (1.0f / NTRI);
        float var  = g_sumbuf[384 + c] * (1.0f / NTRI) - mean * mean;
        float a = gc3[c] * rsqrtf(var + EPSF);
        g_ab[256 + c] = a;
        g_ab[384 + c] = bc3[c] - mean * a;
    }
}

// ============================================================================
// K4: c2 activation: g2 = sigmoid(BN(y2_f)) * tanh(BN(y2_c)), + g2 stats
// One thread per (edge, 4-col group). float4 loads/stores.
// ============================================================================
__global__ void __launch_bounds__(256) k_c2act() {
    __shared__ float sred[128];
    int tid = threadIdx.x;
    if (tid < 128) sred[tid] = 0.0f;
    __syncthreads();
    size_t i0 = (size_t)blockIdx.x * 256 + tid;
    int c = (int)(i0 & 15) * 4;
    float4 af = *(const float4*)&g_ab[c];
    float4 bf = *(const float4*)&g_ab[128 + c];
    float4 ac = *(const float4*)&g_ab[64 + c];
    float4 bc = *(const float4*)&g_ab[192 + c];
    float s[4] = {0, 0, 0, 0}, q[4] = {0, 0, 0, 0};
    size_t stride = (size_t)gridDim.x * 256;
    size_t n = (size_t)NEDGE * 16;
    for (size_t idx = i0; idx < n; idx += stride) {
        size_t e = idx >> 4;
        float4 yf = *(const float4*)&g_y2[(e << 7) + c];
        float4 yc = *(const float4*)&g_y2[(e << 7) + 64 + c];
        float4 g;
        g.x = sigmoidf_(yf.x * af.x + bf.x) * tanhf(yc.x * ac.x + bc.x);
        g.y = sigmoidf_(yf.y * af.y + bf.y) * tanhf(yc.y * ac.y + bc.y);
        g.z = sigmoidf_(yf.z * af.z + bf.z) * tanhf(yc.z * ac.z + bc.z);
        g.w = sigmoidf_(yf.w * af.w + bf.w) * tanhf(yc.w * ac.w + bc.w);
        *(float4*)&g_g2[idx << 2] = g;
        s[0] += g.x; s[1] += g.y; s[2] += g.z; s[3] += g.w;
        q[0] += g.x * g.x; q[1] += g.y * g.y; q[2] += g.z * g.z; q[3] += g.w * g.w;
    }
#pragma unroll
    for (int u = 0; u < 4; u++) {
        atomicAdd(&sred[c + u], s[u]);
        atomicAdd(&sred[64 + c + u], q[u]);
    }
    __syncthreads();
    if (tid < 128) atomicAdd(&g_sumbuf[512 + tid], sred[tid]);
}

// ============================================================================
// K5: c3 activation + segment-sum scatter: agg[iji[t]] += sigmoid*tanh
// One thread per (triplet, 4-col group); vector red.global.add
// ============================================================================
__global__ void __launch_bounds__(256) k_c3act(const int* __restrict__ iji) {
    size_t i0 = (size_t)blockIdx.x * 256 + threadIdx.x;
    int c = (int)(i0 & 15) * 4;
    float4 af = *(const float4*)&g_ab[256 + c];
    float4 bf = *(const float4*)&g_ab[384 + c];
    float4 ac = *(const float4*)&g_ab[320 + c];
    float4 bc = *(const float4*)&g_ab[448 + c];
    size_t stride = (size_t)gridDim.x * 256;
    size_t n = (size_t)NTRI * 16;
    for (size_t idx = i0; idx < n; idx += stride) {
        size_t t = idx >> 4;
        float4 yf = *(const float4*)&g_y3[(t << 7) + c];
        float4 yc = *(const float4*)&g_y3[(t << 7) + 64 + c];
        float m0 = sigmoidf_(yf.x * af.x + bf.x) * tanhf(yc.x * ac.x + bc.x);
        float m1 = sigmoidf_(yf.y * af.y + bf.y) * tanhf(yc.y * ac.y + bc.y);
        float m2 = sigmoidf_(yf.z * af.z + bf.z) * tanhf(yc.z * ac.z + bc.z);
        float m3 = sigmoidf_(yf.w * af.w + bf.w) * tanhf(yc.w * ac.w + bc.w);
        float* dst = g_agg + ((size_t)iji[t] << 6) + c;
        asm volatile("red.global.v4.f32.add [%0], {%1, %2, %3, %4};"
                     :: "l"(dst), "f"(m0), "f"(m1), "f"(m2), "f"(m3) : "memory");
    }
}

// ============================================================================
// K6a: agg column stats (float4)
// ============================================================================
__global__ void __launch_bounds__(256) k_aggstats() {
    __shared__ float sred[128];
    int tid = threadIdx.x;
    if (tid < 128) sred[tid] = 0.0f;
    __syncthreads();
    size_t i0 = (size_t)blockIdx.x * 256 + tid;
    int c = (int)(i0 & 15) * 4;
    float s[4] = {0, 0, 0, 0}, q[4] = {0, 0, 0, 0};
    size_t stride = (size_t)gridDim.x * 256;
    size_t n = (size_t)NEDGE * 16;
    for (size_t idx = i0; idx < n; idx += stride) {
        float4 v = *(const float4*)&g_agg[idx << 2];
        s[0] += v.x; s[1] += v.y; s[2] += v.z; s[3] += v.w;
        q[0] += v.x * v.x; q[1] += v.y * v.y; q[2] += v.z * v.z; q[3] += v.w * v.w;
    }
#pragma unroll
    for (int u = 0; u < 4; u++) {
        atomicAdd(&sred[c + u], s[u]);
        atomicAdd(&sred[64 + c + u], q[u]);
    }
    __syncthreads();
    if (tid < 128) atomicAdd(&g_sumbuf[640 + tid], sred[tid]);
}

// ============================================================================
// K6b: finalize g2 / agg BN coefficients
// ============================================================================
__global__ void k_stats2(const float* __restrict__ g22, const float* __restrict__ b22,
                         const float* __restrict__ g32, const float* __restrict__ b32) {
    int tid = threadIdx.x;  // 128
    if (tid < 64) {
        float mean = g_sumbuf[512 + tid] * (1.0f / NEDGE);
        float var  = g_sumbuf[576 + tid] * (1.0f / NEDGE) - mean * mean;
        float a = g22[tid] * rsqrtf(var + EPSF);
        g_ab[512 + tid] = a;
        g_ab[576 + tid] = b22[tid] - mean * a;
    } else {
        int c = tid - 64;
        float mean = g_sumbuf[640 + c] * (1.0f / NEDGE);
        float var  = g_sumbuf[704 + c] * (1.0f / NEDGE) - mean * mean;
        float a = g32[c] * rsqrtf(var + EPSF);
        g_ab[640 + c] = a;
        g_ab[704 + c] = b32[c] - mean * a;
    }
}

// ============================================================================
// K7: out = tanh(edge + BN(g2) + BN(agg))  (float4)
// ============================================================================
__global__ void __launch_bounds__(256) k_out(const float* __restrict__ edge,
                                             float* __restrict__ out) {
    size_t i0 = (size_t)blockIdx.x * 256 + threadIdx.x;
    int c = (int)(i0 & 15) * 4;
    float4 a2 = *(const float4*)&g_ab[512 + c];
    float4 b2v = *(const float4*)&g_ab[576 + c];
    float4 a3 = *(const float4*)&g_ab[640 + c];
    float4 b3v = *(const float4*)&g_ab[704 + c];
    size_t stride = (size_t)gridDim.x * 256;
    size_t n = (size_t)NEDGE * 16;
    for (size_t idx = i0; idx < n; idx += stride) {
        float4 e = *(const float4*)&edge[idx << 2];
        float4 g = *(const float4*)&g_g2[idx << 2];
        float4 a = *(const float4*)&g_agg[idx << 2];
        float4 o;
        o.x = tanhf(e.x + g.x * a2.x + b2v.x + a.x * a3.x + b3v.x);
        o.y = tanhf(e.y + g.y * a2.y + b2v.y + a.y * a3.y + b3v.y);
        o.z = tanhf(e.z + g.z * a2.z + b2v.z + a.z * a3.z + b3v.z);
        o.w = tanhf(e.w + g.w * a2.w + b2v.w + a.w * a3.w + b3v.w);
        *(float4*)&out[idx << 2] = o;
    }
}

// ============================================================================
extern "C" void kernel_launch(void* const* d_in, const int* in_sizes, int n_in,
                              void* d_out, int out_size) {
    const float* node   = (const float*)d_in[0];
    const float* edge   = (const float*)d_in[1];
    const int* vi       = (const int*)d_in[2];
    const int* vj       = (const int*)d_in[3];
    const int* idx_i    = (const int*)d_in[4];
    const int* idx_j    = (const int*)d_in[5];
    const int* idx_k    = (const int*)d_in[6];
    const int* idx_ji   = (const int*)d_in[7];
    const int* idx_kj   = (const int*)d_in[8];
    const float* W2     = (const float*)d_in[9];
    const float* b2     = (const float*)d_in[10];
    const float* W3     = (const float*)d_in[11];
    const float* b3     = (const float*)d_in[12];
    const float* gc2    = (const float*)d_in[13];
    const float* bc2    = (const float*)d_in[14];
    const float* gc3    = (const float*)d_in[15];
    const float* bc3    = (const float*)d_in[16];
    const float* g22    = (const float*)d_in[17];
    const float* b22    = (const float*)d_in[18];
    const float* g32    = (const float*)d_in[19];
    const float* b32    = (const float*)d_in[20];
    float* out = (float*)d_out;

    const int smem_k3 = (D3 * CC + 48 * 324) * (int)sizeof(float);   // 226048 B
    const int smem_k1 = (64 * CC + 64 * 72) * (int)sizeof(float);    // 51200 B
    cudaFuncSetAttribute(k_c3mm, cudaFuncAttributeMaxDynamicSharedMemorySize, smem_k3);
    cudaFuncSetAttribute(k_c2mm, cudaFuncAttributeMaxDynamicSharedMemorySize, smem_k1);

    k_zero<<<1024, 256>>>();
    k_c2mm<<<592, 256, smem_k1>>>(node, vi, vj, W2, b2);
    k_c3mm<<<148, 256, smem_k3>>>(node, edge, idx_i, idx_j, idx_k, idx_ji, idx_kj, W3, b3);
    k_stats1<<<1, 256>>>(gc2, bc2, gc3, bc3);
    k_c2act<<<512, 256>>>();
    k_c3act<<<2048, 256>>>(idx_ji);
    k_aggstats<<<512, 256>>>();
    k_stats2<<<1, 128>>>(g22, b22, g32, b32);
    k_out<<<512, 256>>>(edge, out);
}